// round 14
// baseline (speedup 1.0000x reference)
#include <cuda_runtime.h>

#define PLANE (128*128)
#define VOL (128*128*128)

// Scratch (device globals — no allocation allowed)
__device__ float g_H[8*VOL];    // 64 MB
__device__ float g_A[8*VOL];    // 64 MB
__device__ float g_W[27*VOL];   // 226 MB: adaptive weights, 27 fp32 tap-planes
__device__ float g_F[VOL];      // 8 MB single-channel ping buffer

typedef unsigned long long u64;
__device__ u64 g_WG[4032];      // Winograd-transformed conv27 weights (32 KB)

// ---- packed f32x2 helpers (f32x2 ops are PTX-only on sm_103a) ----
__device__ __forceinline__ u64 pack2(float lo, float hi){
  u64 r;
  asm("mov.b64 %0, {%1, %2};" : "=l"(r) : "f"(lo), "f"(hi));
  return r;
}
__device__ __forceinline__ void unpack2(float& lo, float& hi, u64 v){
  asm("mov.b64 {%0, %1}, %2;" : "=f"(lo), "=f"(hi) : "l"(v));
}
__device__ __forceinline__ void fma2(u64& d, u64 a, u64 b){
  asm("fma.rn.f32x2 %0, %1, %2, %0;" : "+l"(d) : "l"(a), "l"(b));
}
__device__ __forceinline__ u64 add2(u64 a, u64 b){
  u64 r;
  asm("add.rn.f32x2 %0, %1, %2;" : "=l"(r) : "l"(a), "l"(b));
  return r;
}
__device__ __forceinline__ u64 neg2(u64 a){ return a ^ 0x8000000080000000ULL; }

// ============================================================================
// 3x3x3 conv, CIN=8, SAME padding, channel-planar. (exact R11 version)
// Thread = adjacent w-pair; SMEM weights as ulonglong2 (broadcast LDS.128);
// output-channel pairs accumulate in f32x2. Used for COUT=8 and COUT=1.
// ============================================================================
template<int COUT, bool RELU, bool NORM>
__global__ void __launch_bounds__(128)
conv3d_k(const float* __restrict__ x, const float* __restrict__ wgt,
         const float* __restrict__ bias, float* __restrict__ out)
{
  constexpr int CPH = (COUT + 3) / 4;
  constexpr int CP  = 2*CPH;
  __shared__ ulonglong2 wp[8*27*CPH];
  const int tid = threadIdx.x;
  const int h  = 2*blockIdx.x + (tid >> 6);
  const int w0 = (tid & 63)*2;
  const int d  = blockIdx.y;

  for (int i = tid; i < 8*27*CPH; i += 128){
    int p2 = i % CPH; int rest = i / CPH; int t = rest % 27; int ci = rest / 27;
    float c0 = (4*p2+0 < COUT) ? wgt[((4*p2+0)*8 + ci)*27 + t] : 0.f;
    float c1 = (4*p2+1 < COUT) ? wgt[((4*p2+1)*8 + ci)*27 + t] : 0.f;
    float c2 = (4*p2+2 < COUT) ? wgt[((4*p2+2)*8 + ci)*27 + t] : 0.f;
    float c3 = (4*p2+3 < COUT) ? wgt[((4*p2+3)*8 + ci)*27 + t] : 0.f;
    wp[i] = make_ulonglong2(pack2(c0,c1), pack2(c2,c3));
  }
  __syncthreads();

  u64 acc0[CP], acc1[CP];
  #pragma unroll
  for (int p = 0; p < CP; p++){
    float blo = (bias && 2*p   < COUT) ? bias[2*p]   : 0.f;
    float bhi = (bias && 2*p+1 < COUT) ? bias[2*p+1] : 0.f;
    acc0[p] = pack2(blo, bhi);
    acc1[p] = acc0[p];
  }

  const bool pd[3] = { d > 0, true, d < 127 };
  const bool ph[3] = { h > 0, true, h < 127 };
  const bool pa = w0 > 0, pe = w0 < 126;
  const int base = d*PLANE + h*128 + w0;

  #pragma unroll 1
  for (int ci = 0; ci < 8; ci++){
    const float* b = x + ci*VOL + base;
    const ulonglong2* wci = wp + ci*27*CPH;
    #pragma unroll
    for (int i = 0; i < 3; i++){
      #pragma unroll
      for (int j = 0; j < 3; j++){
        const int OFF = (i-1)*PLANE + (j-1)*128;
        const bool vr = pd[i] && ph[j];
        float2 bc = make_float2(0.f, 0.f);
        float av = 0.f, dv = 0.f;
        if (vr)       bc = *reinterpret_cast<const float2*>(b + OFF);
        if (vr && pa) av = __ldg(b + OFF - 1);
        if (vr && pe) dv = __ldg(b + OFF + 2);
        u64 va = pack2(av,av), vb = pack2(bc.x,bc.x), vc = pack2(bc.y,bc.y), vd = pack2(dv,dv);
        const ulonglong2* wt = wci + (i*9 + j*3)*CPH;
        #pragma unroll
        for (int k = 0; k < 3; k++){
          u64 q0 = (k==0) ? va : (k==1) ? vb : vc;
          u64 q1 = (k==0) ? vb : (k==1) ? vc : vd;
          #pragma unroll
          for (int p2 = 0; p2 < CPH; p2++){
            ulonglong2 wv = wt[k*CPH + p2];
            fma2(acc0[2*p2  ], q0, wv.x);
            fma2(acc0[2*p2+1], q0, wv.y);
            fma2(acc1[2*p2  ], q1, wv.x);
            fma2(acc1[2*p2+1], q1, wv.y);
          }
        }
      }
    }
  }

  float r0[2*CP], r1[2*CP];
  #pragma unroll
  for (int p = 0; p < CP; p++){
    unpack2(r0[2*p], r0[2*p+1], acc0[p]);
    unpack2(r1[2*p], r1[2*p+1], acc1[p]);
  }
  if (RELU){
    #pragma unroll
    for (int c = 0; c < COUT; c++){ r0[c] = fmaxf(r0[c],0.f); r1[c] = fmaxf(r1[c],0.f); }
  }

  if (NORM){
    float s0 = 0.f, s1 = 0.f;
    #pragma unroll
    for (int c = 0; c < COUT; c++){ s0 += fabsf(r0[c]); s1 += fabsf(r1[c]); }
    float i0 = 1.f / fmaxf(s0, 1e-12f);
    float i1 = 1.f / fmaxf(s1, 1e-12f);
    #pragma unroll
    for (int c = 0; c < COUT; c++){
      float2 o; o.x = r0[c]*i0; o.y = r1[c]*i1;
      *reinterpret_cast<float2*>(out + c*VOL + base) = o;
    }
  } else {
    #pragma unroll
    for (int c = 0; c < COUT; c++){
      float2 o; o.x = r0[c]; o.y = r1[c];
      *reinterpret_cast<float2*>(out + c*VOL + base) = o;
    }
  }
}

// ============================================================================
// Winograd F(2,3) weight transform for the 8->27 conv (w axis).
// gw0=g0, gw1=(g0+g1+g2)/2, gw2=(g0-g1+g2)/2, gw3=g2.
// Layout (u64 = {co0,co1} f32x2):
//   pass A (ch 0..15):  IA = ((ci*9+r)*4+t)*8 + s,  co0 = 2s,       s<8
//   pass B (ch16..27p): IB = 2304 + ((ci*9+r)*4+t)*6 + s, co0=16+2s, s<6
// ============================================================================
__global__ void wino_wgt_k(const float* __restrict__ wgt, u64* __restrict__ wg)
{
  const int e = blockIdx.x*128 + threadIdx.x;
  if (e >= 4032) return;
  int s, t, r, ci, co0;
  if (e < 2304){
    s = e & 7; t = (e >> 3) & 3; r = (e >> 5) % 9; ci = e / 288; co0 = 2*s;
  } else {
    int f = e - 2304;
    s = f % 6; t = (f/6) & 3; r = (f/24) % 9; ci = f / 216; co0 = 16 + 2*s;
  }
  float gv[2];
  #pragma unroll
  for (int q = 0; q < 2; q++){
    int co = co0 + q;
    float g0 = 0.f, g1 = 0.f, g2 = 0.f;
    if (co < 27){
      const float* gp = wgt + (co*8 + ci)*27 + r*3;
      g0 = gp[0]; g1 = gp[1]; g2 = gp[2];
    }
    gv[q] = (t==0) ? g0 : (t==1) ? 0.5f*(g0+g1+g2) : (t==2) ? 0.5f*(g0-g1+g2) : g2;
  }
  wg[e] = pack2(gv[0], gv[1]);
}

// ============================================================================
// conv 8->27 + L1-normalize via Winograd F(2,3) along w.
// Thread = w-pair (2 outputs from the 4-wide window d0..d3 it already loads).
// t0=d0-d2, t1=d1+d2, t2=d2-d1, t3n=d3-d1 (pre-negated); m_t = gw_t * t_t
// accumulated over (ci, d-tap, h-tap); y0 = M0+M1+M2, y1 = M1-M2+M3n.
// Two channel passes (0..15, 16..26+pad) to keep M in registers.
// ============================================================================
__global__ void __launch_bounds__(128)
conv27_wino_k(const float* __restrict__ x, const u64* __restrict__ wg,
              float* __restrict__ out)
{
  __shared__ u64 ws[4032];
  const int tid = threadIdx.x;
  const int h  = 2*blockIdx.x + (tid >> 6);
  const int w0 = (tid & 63)*2;
  const int d  = blockIdx.y;

  {
    const ulonglong2* src = reinterpret_cast<const ulonglong2*>(wg);
    ulonglong2* dst = reinterpret_cast<ulonglong2*>(ws);
    for (int i = tid; i < 2016; i += 128) dst[i] = src[i];
  }
  __syncthreads();

  const bool pd[3] = { d > 0, true, d < 127 };
  const bool ph[3] = { h > 0, true, h < 127 };
  const bool pa = w0 > 0, pe = w0 < 126;
  const int base = d*PLANE + h*128 + w0;

  u64 yA0[8], yA1[8], yB0[6], yB1[6];

  // ---------------- pass A: channels 0..15 ----------------
  {
    u64 M[32];
    #pragma unroll
    for (int m = 0; m < 32; m++) M[m] = 0ull;

    #pragma unroll 1
    for (int ci = 0; ci < 8; ci++){
      const float* b = x + ci*VOL + base;
      #pragma unroll
      for (int r = 0; r < 9; r++){
        const int i = r/3, j = r%3;
        const int OFF = (i-1)*PLANE + (j-1)*128;
        const bool vr = pd[i] && ph[j];
        float2 bc = make_float2(0.f, 0.f);
        float av = 0.f, dv = 0.f;
        if (vr)       bc = *reinterpret_cast<const float2*>(b + OFF);
        if (vr && pa) av = __ldg(b + OFF - 1);
        if (vr && pe) dv = __ldg(b + OFF + 2);
        const float t0 = av - bc.y;
        const float t1 = bc.x + bc.y;
        const float t2 = bc.y - bc.x;
        const float t3 = dv - bc.x;          // pre-negated t3
        u64 T[4] = { pack2(t0,t0), pack2(t1,t1), pack2(t2,t2), pack2(t3,t3) };
        const ulonglong2* wt = reinterpret_cast<const ulonglong2*>(ws) + (ci*9 + r)*16;
        #pragma unroll
        for (int t = 0; t < 4; t++){
          #pragma unroll
          for (int q = 0; q < 4; q++){
            ulonglong2 wv = wt[t*4 + q];
            fma2(M[t*8 + 2*q  ], T[t], wv.x);
            fma2(M[t*8 + 2*q+1], T[t], wv.y);
          }
        }
      }
    }
    #pragma unroll
    for (int s = 0; s < 8; s++){
      yA0[s] = add2(add2(M[s], M[8+s]), M[16+s]);
      yA1[s] = add2(add2(M[8+s], neg2(M[16+s])), M[24+s]);
    }
  }

  // ---------------- pass B: channels 16..26 (+pad) ----------------
  {
    u64 M[24];
    #pragma unroll
    for (int m = 0; m < 24; m++) M[m] = 0ull;

    #pragma unroll 1
    for (int ci = 0; ci < 8; ci++){
      const float* b = x + ci*VOL + base;
      #pragma unroll
      for (int r = 0; r < 9; r++){
        const int i = r/3, j = r%3;
        const int OFF = (i-1)*PLANE + (j-1)*128;
        const bool vr = pd[i] && ph[j];
        float2 bc = make_float2(0.f, 0.f);
        float av = 0.f, dv = 0.f;
        if (vr)       bc = *reinterpret_cast<const float2*>(b + OFF);
        if (vr && pa) av = __ldg(b + OFF - 1);
        if (vr && pe) dv = __ldg(b + OFF + 2);
        const float t0 = av - bc.y;
        const float t1 = bc.x + bc.y;
        const float t2 = bc.y - bc.x;
        const float t3 = dv - bc.x;
        u64 T[4] = { pack2(t0,t0), pack2(t1,t1), pack2(t2,t2), pack2(t3,t3) };
        const ulonglong2* wt = reinterpret_cast<const ulonglong2*>(ws) + 1152 + (ci*9 + r)*12;
        #pragma unroll
        for (int t = 0; t < 4; t++){
          #pragma unroll
          for (int q = 0; q < 3; q++){
            ulonglong2 wv = wt[t*3 + q];
            fma2(M[t*6 + 2*q  ], T[t], wv.x);
            fma2(M[t*6 + 2*q+1], T[t], wv.y);
          }
        }
      }
    }
    #pragma unroll
    for (int s = 0; s < 6; s++){
      yB0[s] = add2(add2(M[s], M[6+s]), M[12+s]);
      yB1[s] = add2(add2(M[6+s], neg2(M[12+s])), M[18+s]);
    }
  }

  // ---------------- L1-normalize over 27 channels + store ----------------
  float r0[28], r1[28];
  #pragma unroll
  for (int s = 0; s < 8; s++){
    unpack2(r0[2*s], r0[2*s+1], yA0[s]);
    unpack2(r1[2*s], r1[2*s+1], yA1[s]);
  }
  #pragma unroll
  for (int s = 0; s < 6; s++){
    unpack2(r0[16+2*s], r0[16+2*s+1], yB0[s]);
    unpack2(r1[16+2*s], r1[16+2*s+1], yB1[s]);
  }
  float s0 = 0.f, s1 = 0.f;
  #pragma unroll
  for (int c = 0; c < 27; c++){ s0 += fabsf(r0[c]); s1 += fabsf(r1[c]); }
  const float i0 = 1.f / fmaxf(s0, 1e-12f);
  const float i1 = 1.f / fmaxf(s1, 1e-12f);
  #pragma unroll
  for (int c = 0; c < 27; c++){
    float2 o; o.x = r0[c]*i0; o.y = r1[c]*i1;
    *reinterpret_cast<float2*>(out + c*VOL + base) = o;
  }
}

// ============================================================================
// Adaptive conv, SMEM-tiled, channel-pair fma2. (R11 winner, unchanged.)
// ============================================================================
template<int C, bool TANH>
__global__ void __launch_bounds__(256)
adapt_k(const float* __restrict__ x, const float* __restrict__ w27,
        float* __restrict__ out)
{
  const int tid = threadIdx.x;
  const int h0 = 2*blockIdx.x;
  const int d  = blockIdx.y;
  const int hs = tid >> 7;
  const int w  = tid & 127;
  const int idx = d*PLANE + (h0+hs)*128 + w;

  if constexpr (C == 8){
    __shared__ float2 tile[48*128];
    {
      const int sub  = tid >> 6;
      const int lane = tid & 63;
      #pragma unroll
      for (int it = 0; it < 12; it++){
        const int row = it*4 + sub;
        const int cp  = (row*43) >> 9;
        const int rm  = row - cp*12;
        const int di  = rm >> 2;
        const int hi  = rm & 3;
        const int dd  = d + di - 1;
        const int hh  = h0 + hi - 1;
        float2 a = make_float2(0.f,0.f), b = make_float2(0.f,0.f);
        if ((unsigned)dd < 128u && (unsigned)hh < 128u){
          const float* p0 = x + (2*cp)*VOL + (dd*128 + hh)*128 + lane*2;
          a = *reinterpret_cast<const float2*>(p0);
          b = *reinterpret_cast<const float2*>(p0 + VOL);
        }
        float4 st = make_float4(a.x, b.x, a.y, b.y);
        *reinterpret_cast<float4*>(tile + row*128 + lane*2) = st;
      }
    }

    float wv[27];
    #pragma unroll
    for (int t = 0; t < 27; t++) wv[t] = __ldg(w27 + t*VOL + idx);

    __syncthreads();

    const bool wa = (w > 0), we = (w < 127);
    u64 acc[4] = {0ull,0ull,0ull,0ull};

    #pragma unroll
    for (int i = 0; i < 3; i++){
      #pragma unroll
      for (int j = 0; j < 3; j++){
        const float2* rp = tile + (i*4 + hs + j)*128 + w;
        #pragma unroll
        for (int k = 0; k < 3; k++){
          const int t = i*9 + j*3 + k;
          const u64 wpk = pack2(wv[t], wv[t]);
          const bool ok = (k==0) ? wa : (k==2) ? we : true;
          #pragma unroll
          for (int cp = 0; cp < 4; cp++){
            float2 v = make_float2(0.f,0.f);
            if (ok) v = rp[cp*1536 + (k-1)];
            fma2(acc[cp], wpk, *reinterpret_cast<const u64*>(&v));
          }
        }
      }
    }

    #pragma unroll
    for (int cp = 0; cp < 4; cp++){
      float r0, r1; unpack2(r0, r1, acc[cp]);
      out[(2*cp  )*VOL + idx] = TANH ? tanhf(r0) : r0;
      out[(2*cp+1)*VOL + idx] = TANH ? tanhf(r1) : r1;
    }
  } else {
    __shared__ float tile[12*128];
    {
      const int sub  = tid >> 5;
      const int lane = tid & 31;
      #pragma unroll
      for (int it = 0; it < 2; it++){
        const int row = it*8 + sub;
        if (row < 12){
          const int di = row >> 2, hi = row & 3;
          const int dd = d + di - 1, hh = h0 + hi - 1;
          float4 v = make_float4(0.f,0.f,0.f,0.f);
          if ((unsigned)dd < 128u && (unsigned)hh < 128u)
            v = *reinterpret_cast<const float4*>(x + (dd*128 + hh)*128 + lane*4);
          *reinterpret_cast<float4*>(tile + row*128 + lane*4) = v;
        }
      }
    }

    float wv[27];
    #pragma unroll
    for (int t = 0; t < 27; t++) wv[t] = __ldg(w27 + t*VOL + idx);

    __syncthreads();

    const bool wa = (w > 0), we = (w < 127);
    float s0 = 0.f, s1 = 0.f, s2 = 0.f;
    #pragma unroll
    for (int i = 0; i < 3; i++){
      #pragma unroll
      for (int j = 0; j < 3; j++){
        const float* rp = tile + (i*4 + hs + j)*128 + w;
        const int t = i*9 + j*3;
        float va = 0.f, vc = 0.f;
        if (wa) va = rp[-1];
        if (we) vc = rp[ 1];
        s0 = fmaf(wv[t  ], va,    s0);
        s1 = fmaf(wv[t+1], rp[0], s1);
        s2 = fmaf(wv[t+2], vc,    s2);
      }
    }
    float acc = s0 + s1 + s2;
    out[idx] = TANH ? tanhf(acc) : acc;
  }
}

extern "C" void kernel_launch(void* const* d_in, const int* in_sizes, int n_in,
                              void* d_out, int out_size)
{
  const float* x    = (const float*)d_in[0];
  const float* a1w1 = (const float*)d_in[1];
  const float* a1b1 = (const float*)d_in[2];
  const float* a1w2 = (const float*)d_in[3];
  const float* a2w1 = (const float*)d_in[4];
  const float* a2b1 = (const float*)d_in[5];
  const float* a2w2 = (const float*)d_in[6];
  const float* a3w1 = (const float*)d_in[7];
  const float* a3b1 = (const float*)d_in[8];
  const float* a3w2 = (const float*)d_in[9];
  const float* midw = (const float*)d_in[10];
  const float* midb = (const float*)d_in[11];
  const float* outw = (const float*)d_in[12];
  const float* outb = (const float*)d_in[13];
  float* y = (float*)d_out;

  float *H, *A, *W, *F; u64 *WG;
  cudaGetSymbolAddress((void**)&H, g_H);
  cudaGetSymbolAddress((void**)&A, g_A);
  cudaGetSymbolAddress((void**)&W, g_W);
  cudaGetSymbolAddress((void**)&F, g_F);
  cudaGetSymbolAddress((void**)&WG, g_WG);

  dim3 gc(64, 128), bc(128);        // conv: h-pair x d; thread = w-pair
  dim3 ga(64, 128), ba(256);        // adapt: h-pair x d; thread = voxel

  // ---- adaptive block 1 (input x) ----
  conv3d_k<8,  true,  false><<<gc,bc>>>(x, a1w1, a1b1, H);     // h1
  wino_wgt_k<<<32,128>>>(a1w2, WG);
  conv27_wino_k<<<gc,bc>>>(H, WG, W);                          // weight field
  adapt_k<8, false><<<ga,ba>>>(x, W, A);
  adapt_k<8, false><<<ga,ba>>>(A, W, H);
  adapt_k<8, false><<<ga,ba>>>(H, W, A);                       // block1 out = A

  // ---- mid conv ----
  conv3d_k<8, false, false><<<gc,bc>>>(A, midw, midb, H);      // mid = H

  // ---- adaptive block 2 (input mid) ----
  conv3d_k<8,  true,  false><<<gc,bc>>>(H, a2w1, a2b1, A);     // h2
  wino_wgt_k<<<32,128>>>(a2w2, WG);
  conv27_wino_k<<<gc,bc>>>(A, WG, W);
  adapt_k<8, false><<<ga,ba>>>(H, W, A);
  adapt_k<8, false><<<ga,ba>>>(A, W, H);
  adapt_k<8, false><<<ga,ba>>>(H, W, A);                       // mid2 = A

  // ---- out conv + adaptive block 3 (weights from mid2, data 1-channel) ----
  conv3d_k<1, false, false><<<gc,bc>>>(A, outw, outb, F);      // final (1ch)
  conv3d_k<8, true,  false><<<gc,bc>>>(A, a3w1, a3b1, H);      // h3 from mid2
  wino_wgt_k<<<32,128>>>(a3w2, WG);
  conv27_wino_k<<<gc,bc>>>(H, WG, W);
  adapt_k<1, false><<<ga,ba>>>(F, W, y);
  adapt_k<1, false><<<ga,ba>>>(y, W, F);
  adapt_k<1, true ><<<ga,ba>>>(F, W, y);                       // + tanh
}

// round 15
// speedup vs baseline: 1.2703x; 1.2703x over previous
#include <cuda_runtime.h>

#define PLANE (128*128)
#define VOL (128*128*128)

// Scratch (device globals — no allocation allowed)
__device__ float g_H[8*VOL];    // 64 MB
__device__ float g_A[8*VOL];    // 64 MB
__device__ float g_W[27*VOL];   // 226 MB: adaptive weights, 27 fp32 tap-planes
__device__ float g_F[VOL];      // 8 MB single-channel ping buffer

typedef unsigned long long u64;

// ---- packed f32x2 helpers (FFMA2 is PTX-only on sm_103a) ----
__device__ __forceinline__ u64 pack2(float lo, float hi){
  u64 r;
  asm("mov.b64 %0, {%1, %2};" : "=l"(r) : "f"(lo), "f"(hi));
  return r;
}
__device__ __forceinline__ void unpack2(float& lo, float& hi, u64 v){
  asm("mov.b64 {%0, %1}, %2;" : "=f"(lo), "=f"(hi) : "l"(v));
}
__device__ __forceinline__ void fma2(u64& d, u64 a, u64 b){
  asm("fma.rn.f32x2 %0, %1, %2, %0;" : "+l"(d) : "l"(a), "l"(b));
}

// No-op shim: shifts launch indices so ncu's capture (5th launch) lands on
// the 27-channel conv instead of adapt_k. Deterministic, no memory effects.
__global__ void noop_k(){}

// ============================================================================
// 3x3x3 conv, CIN=8, SAME padding, channel-planar. (exact R11 version)
// Thread = adjacent w-pair; SMEM weights as ulonglong2 (broadcast LDS.128);
// output-channel pairs accumulate in f32x2.
// ============================================================================
template<int COUT, bool RELU, bool NORM>
__global__ void __launch_bounds__(128)
conv3d_k(const float* __restrict__ x, const float* __restrict__ wgt,
         const float* __restrict__ bias, float* __restrict__ out)
{
  constexpr int CPH = (COUT + 3) / 4;
  constexpr int CP  = 2*CPH;
  __shared__ ulonglong2 wp[8*27*CPH];
  const int tid = threadIdx.x;
  const int h  = 2*blockIdx.x + (tid >> 6);
  const int w0 = (tid & 63)*2;
  const int d  = blockIdx.y;

  for (int i = tid; i < 8*27*CPH; i += 128){
    int p2 = i % CPH; int rest = i / CPH; int t = rest % 27; int ci = rest / 27;
    float c0 = (4*p2+0 < COUT) ? wgt[((4*p2+0)*8 + ci)*27 + t] : 0.f;
    float c1 = (4*p2+1 < COUT) ? wgt[((4*p2+1)*8 + ci)*27 + t] : 0.f;
    float c2 = (4*p2+2 < COUT) ? wgt[((4*p2+2)*8 + ci)*27 + t] : 0.f;
    float c3 = (4*p2+3 < COUT) ? wgt[((4*p2+3)*8 + ci)*27 + t] : 0.f;
    wp[i] = make_ulonglong2(pack2(c0,c1), pack2(c2,c3));
  }
  __syncthreads();

  u64 acc0[CP], acc1[CP];
  #pragma unroll
  for (int p = 0; p < CP; p++){
    float blo = (bias && 2*p   < COUT) ? bias[2*p]   : 0.f;
    float bhi = (bias && 2*p+1 < COUT) ? bias[2*p+1] : 0.f;
    acc0[p] = pack2(blo, bhi);
    acc1[p] = acc0[p];
  }

  const bool pd[3] = { d > 0, true, d < 127 };
  const bool ph[3] = { h > 0, true, h < 127 };
  const bool pa = w0 > 0, pe = w0 < 126;
  const int base = d*PLANE + h*128 + w0;

  #pragma unroll 1
  for (int ci = 0; ci < 8; ci++){
    const float* b = x + ci*VOL + base;
    const ulonglong2* wci = wp + ci*27*CPH;
    #pragma unroll
    for (int i = 0; i < 3; i++){
      #pragma unroll
      for (int j = 0; j < 3; j++){
        const int OFF = (i-1)*PLANE + (j-1)*128;
        const bool vr = pd[i] && ph[j];
        float2 bc = make_float2(0.f, 0.f);
        float av = 0.f, dv = 0.f;
        if (vr)       bc = *reinterpret_cast<const float2*>(b + OFF);
        if (vr && pa) av = __ldg(b + OFF - 1);
        if (vr && pe) dv = __ldg(b + OFF + 2);
        u64 va = pack2(av,av), vb = pack2(bc.x,bc.x), vc = pack2(bc.y,bc.y), vd = pack2(dv,dv);
        const ulonglong2* wt = wci + (i*9 + j*3)*CPH;
        #pragma unroll
        for (int k = 0; k < 3; k++){
          u64 q0 = (k==0) ? va : (k==1) ? vb : vc;
          u64 q1 = (k==0) ? vb : (k==1) ? vc : vd;
          #pragma unroll
          for (int p2 = 0; p2 < CPH; p2++){
            ulonglong2 wv = wt[k*CPH + p2];
            fma2(acc0[2*p2  ], q0, wv.x);
            fma2(acc0[2*p2+1], q0, wv.y);
            fma2(acc1[2*p2  ], q1, wv.x);
            fma2(acc1[2*p2+1], q1, wv.y);
          }
        }
      }
    }
  }

  float r0[2*CP], r1[2*CP];
  #pragma unroll
  for (int p = 0; p < CP; p++){
    unpack2(r0[2*p], r0[2*p+1], acc0[p]);
    unpack2(r1[2*p], r1[2*p+1], acc1[p]);
  }
  if (RELU){
    #pragma unroll
    for (int c = 0; c < COUT; c++){ r0[c] = fmaxf(r0[c],0.f); r1[c] = fmaxf(r1[c],0.f); }
  }

  if (NORM){
    float s0 = 0.f, s1 = 0.f;
    #pragma unroll
    for (int c = 0; c < COUT; c++){ s0 += fabsf(r0[c]); s1 += fabsf(r1[c]); }
    float i0 = 1.f / fmaxf(s0, 1e-12f);
    float i1 = 1.f / fmaxf(s1, 1e-12f);
    #pragma unroll
    for (int c = 0; c < COUT; c++){
      float2 o; o.x = r0[c]*i0; o.y = r1[c]*i1;
      *reinterpret_cast<float2*>(out + c*VOL + base) = o;
    }
  } else {
    #pragma unroll
    for (int c = 0; c < COUT; c++){
      float2 o; o.x = r0[c]; o.y = r1[c];
      *reinterpret_cast<float2*>(out + c*VOL + base) = o;
    }
  }
}

// ============================================================================
// Adaptive conv, SMEM-tiled, channel-pair fma2. (R11 winner, unchanged.)
// ============================================================================
template<int C, bool TANH>
__global__ void __launch_bounds__(256)
adapt_k(const float* __restrict__ x, const float* __restrict__ w27,
        float* __restrict__ out)
{
  const int tid = threadIdx.x;
  const int h0 = 2*blockIdx.x;
  const int d  = blockIdx.y;
  const int hs = tid >> 7;
  const int w  = tid & 127;
  const int idx = d*PLANE + (h0+hs)*128 + w;

  if constexpr (C == 8){
    __shared__ float2 tile[48*128];
    {
      const int sub  = tid >> 6;
      const int lane = tid & 63;
      #pragma unroll
      for (int it = 0; it < 12; it++){
        const int row = it*4 + sub;
        const int cp  = (row*43) >> 9;
        const int rm  = row - cp*12;
        const int di  = rm >> 2;
        const int hi  = rm & 3;
        const int dd  = d + di - 1;
        const int hh  = h0 + hi - 1;
        float2 a = make_float2(0.f,0.f), b = make_float2(0.f,0.f);
        if ((unsigned)dd < 128u && (unsigned)hh < 128u){
          const float* p0 = x + (2*cp)*VOL + (dd*128 + hh)*128 + lane*2;
          a = *reinterpret_cast<const float2*>(p0);
          b = *reinterpret_cast<const float2*>(p0 + VOL);
        }
        float4 st = make_float4(a.x, b.x, a.y, b.y);
        *reinterpret_cast<float4*>(tile + row*128 + lane*2) = st;
      }
    }

    float wv[27];
    #pragma unroll
    for (int t = 0; t < 27; t++) wv[t] = __ldg(w27 + t*VOL + idx);

    __syncthreads();

    const bool wa = (w > 0), we = (w < 127);
    u64 acc[4] = {0ull,0ull,0ull,0ull};

    #pragma unroll
    for (int i = 0; i < 3; i++){
      #pragma unroll
      for (int j = 0; j < 3; j++){
        const float2* rp = tile + (i*4 + hs + j)*128 + w;
        #pragma unroll
        for (int k = 0; k < 3; k++){
          const int t = i*9 + j*3 + k;
          const u64 wpk = pack2(wv[t], wv[t]);
          const bool ok = (k==0) ? wa : (k==2) ? we : true;
          #pragma unroll
          for (int cp = 0; cp < 4; cp++){
            float2 v = make_float2(0.f,0.f);
            if (ok) v = rp[cp*1536 + (k-1)];
            fma2(acc[cp], wpk, *reinterpret_cast<const u64*>(&v));
          }
        }
      }
    }

    #pragma unroll
    for (int cp = 0; cp < 4; cp++){
      float r0, r1; unpack2(r0, r1, acc[cp]);
      out[(2*cp  )*VOL + idx] = TANH ? tanhf(r0) : r0;
      out[(2*cp+1)*VOL + idx] = TANH ? tanhf(r1) : r1;
    }
  } else {
    __shared__ float tile[12*128];
    {
      const int sub  = tid >> 5;
      const int lane = tid & 31;
      #pragma unroll
      for (int it = 0; it < 2; it++){
        const int row = it*8 + sub;
        if (row < 12){
          const int di = row >> 2, hi = row & 3;
          const int dd = d + di - 1, hh = h0 + hi - 1;
          float4 v = make_float4(0.f,0.f,0.f,0.f);
          if ((unsigned)dd < 128u && (unsigned)hh < 128u)
            v = *reinterpret_cast<const float4*>(x + (dd*128 + hh)*128 + lane*4);
          *reinterpret_cast<float4*>(tile + row*128 + lane*4) = v;
        }
      }
    }

    float wv[27];
    #pragma unroll
    for (int t = 0; t < 27; t++) wv[t] = __ldg(w27 + t*VOL + idx);

    __syncthreads();

    const bool wa = (w > 0), we = (w < 127);
    float s0 = 0.f, s1 = 0.f, s2 = 0.f;
    #pragma unroll
    for (int i = 0; i < 3; i++){
      #pragma unroll
      for (int j = 0; j < 3; j++){
        const float* rp = tile + (i*4 + hs + j)*128 + w;
        const int t = i*9 + j*3;
        float va = 0.f, vc = 0.f;
        if (wa) va = rp[-1];
        if (we) vc = rp[ 1];
        s0 = fmaf(wv[t  ], va,    s0);
        s1 = fmaf(wv[t+1], rp[0], s1);
        s2 = fmaf(wv[t+2], vc,    s2);
      }
    }
    float acc = s0 + s1 + s2;
    out[idx] = TANH ? tanhf(acc) : acc;
  }
}

extern "C" void kernel_launch(void* const* d_in, const int* in_sizes, int n_in,
                              void* d_out, int out_size)
{
  const float* x    = (const float*)d_in[0];
  const float* a1w1 = (const float*)d_in[1];
  const float* a1b1 = (const float*)d_in[2];
  const float* a1w2 = (const float*)d_in[3];
  const float* a2w1 = (const float*)d_in[4];
  const float* a2b1 = (const float*)d_in[5];
  const float* a2w2 = (const float*)d_in[6];
  const float* a3w1 = (const float*)d_in[7];
  const float* a3b1 = (const float*)d_in[8];
  const float* a3w2 = (const float*)d_in[9];
  const float* midw = (const float*)d_in[10];
  const float* midb = (const float*)d_in[11];
  const float* outw = (const float*)d_in[12];
  const float* outb = (const float*)d_in[13];
  float* y = (float*)d_out;

  float *H, *A, *W, *F;
  cudaGetSymbolAddress((void**)&H, g_H);
  cudaGetSymbolAddress((void**)&A, g_A);
  cudaGetSymbolAddress((void**)&W, g_W);
  cudaGetSymbolAddress((void**)&F, g_F);

  dim3 gc(64, 128), bc(128);        // conv: h-pair x d; thread = w-pair
  dim3 ga(64, 128), ba(256);        // adapt: h-pair x d; thread = voxel

  // Profiling shims: make the 5th launch (ncu capture target) the 27-ch conv.
  noop_k<<<1,32>>>();
  noop_k<<<1,32>>>();
  noop_k<<<1,32>>>();

  // ---- adaptive block 1 (input x) ----
  conv3d_k<8,  true,  false><<<gc,bc>>>(x, a1w1, a1b1, H);     // h1      (4th)
  conv3d_k<27, false, true ><<<gc,bc>>>(H, a1w2, nullptr, W);  // W field (5th = profiled)
  adapt_k<8, false><<<ga,ba>>>(x, W, A);
  adapt_k<8, false><<<ga,ba>>>(A, W, H);
  adapt_k<8, false><<<ga,ba>>>(H, W, A);                       // block1 out = A

  // ---- mid conv ----
  conv3d_k<8, false, false><<<gc,bc>>>(A, midw, midb, H);      // mid = H

  // ---- adaptive block 2 (input mid) ----
  conv3d_k<8,  true,  false><<<gc,bc>>>(H, a2w1, a2b1, A);     // h2
  conv3d_k<27, false, true ><<<gc,bc>>>(A, a2w2, nullptr, W);
  adapt_k<8, false><<<ga,ba>>>(H, W, A);
  adapt_k<8, false><<<ga,ba>>>(A, W, H);
  adapt_k<8, false><<<ga,ba>>>(H, W, A);                       // mid2 = A

  // ---- out conv + adaptive block 3 (weights from mid2, data 1-channel) ----
  conv3d_k<1, false, false><<<gc,bc>>>(A, outw, outb, F);      // final (1ch)
  conv3d_k<8, true,  false><<<gc,bc>>>(A, a3w1, a3b1, H);      // h3 from mid2
  conv3d_k<27, false, true ><<<gc,bc>>>(H, a3w2, nullptr, W);
  adapt_k<1, false><<<ga,ba>>>(F, W, y);
  adapt_k<1, false><<<ga,ba>>>(y, W, F);
  adapt_k<1, true ><<<ga,ba>>>(F, W, y);                       // + tanh
}

// round 17
// speedup vs baseline: 1.3198x; 1.0390x over previous
#include <cuda_runtime.h>

#define PLANE (128*128)
#define VOL (128*128*128)

// Scratch (device globals — no allocation allowed)
__device__ float g_H[8*VOL];    // 64 MB
__device__ float g_A[8*VOL];    // 64 MB
__device__ float g_W[27*VOL];   // 226 MB: adaptive weights, 27 fp32 tap-planes
__device__ float g_F[VOL];      // 8 MB single-channel ping buffer

typedef unsigned long long u64;

// ---- packed f32x2 helpers (FFMA2 is PTX-only on sm_103a) ----
__device__ __forceinline__ u64 pack2(float lo, float hi){
  u64 r;
  asm("mov.b64 %0, {%1, %2};" : "=l"(r) : "f"(lo), "f"(hi));
  return r;
}
__device__ __forceinline__ void unpack2(float& lo, float& hi, u64 v){
  asm("mov.b64 {%0, %1}, %2;" : "=f"(lo), "=f"(hi) : "l"(v));
}
__device__ __forceinline__ void fma2(u64& d, u64 a, u64 b){
  asm("fma.rn.f32x2 %0, %1, %2, %0;" : "+l"(d) : "l"(a), "l"(b));
}

// Profiler-aiming shim (capture slot = 4th launch).
__global__ void noop_k(){}

// ============================================================================
// 3x3x3 conv, CIN=8, 2-voxel threads. (R11 version — used for COUT=27 only;
// 27 channels can't afford 4-voxel register pressure.)
// ============================================================================
template<int COUT, bool RELU, bool NORM>
__global__ void __launch_bounds__(128)
conv3d_k(const float* __restrict__ x, const float* __restrict__ wgt,
         const float* __restrict__ bias, float* __restrict__ out)
{
  constexpr int CPH = (COUT + 3) / 4;
  constexpr int CP  = 2*CPH;
  __shared__ ulonglong2 wp[8*27*CPH];
  const int tid = threadIdx.x;
  const int h  = 2*blockIdx.x + (tid >> 6);
  const int w0 = (tid & 63)*2;
  const int d  = blockIdx.y;

  for (int i = tid; i < 8*27*CPH; i += 128){
    int p2 = i % CPH; int rest = i / CPH; int t = rest % 27; int ci = rest / 27;
    float c0 = (4*p2+0 < COUT) ? wgt[((4*p2+0)*8 + ci)*27 + t] : 0.f;
    float c1 = (4*p2+1 < COUT) ? wgt[((4*p2+1)*8 + ci)*27 + t] : 0.f;
    float c2 = (4*p2+2 < COUT) ? wgt[((4*p2+2)*8 + ci)*27 + t] : 0.f;
    float c3 = (4*p2+3 < COUT) ? wgt[((4*p2+3)*8 + ci)*27 + t] : 0.f;
    wp[i] = make_ulonglong2(pack2(c0,c1), pack2(c2,c3));
  }
  __syncthreads();

  u64 acc0[CP], acc1[CP];
  #pragma unroll
  for (int p = 0; p < CP; p++){
    float blo = (bias && 2*p   < COUT) ? bias[2*p]   : 0.f;
    float bhi = (bias && 2*p+1 < COUT) ? bias[2*p+1] : 0.f;
    acc0[p] = pack2(blo, bhi);
    acc1[p] = acc0[p];
  }

  const bool pd[3] = { d > 0, true, d < 127 };
  const bool ph[3] = { h > 0, true, h < 127 };
  const bool pa = w0 > 0, pe = w0 < 126;
  const int base = d*PLANE + h*128 + w0;

  #pragma unroll 1
  for (int ci = 0; ci < 8; ci++){
    const float* b = x + ci*VOL + base;
    const ulonglong2* wci = wp + ci*27*CPH;
    #pragma unroll
    for (int i = 0; i < 3; i++){
      #pragma unroll
      for (int j = 0; j < 3; j++){
        const int OFF = (i-1)*PLANE + (j-1)*128;
        const bool vr = pd[i] && ph[j];
        float2 bc = make_float2(0.f, 0.f);
        float av = 0.f, dv = 0.f;
        if (vr)       bc = *reinterpret_cast<const float2*>(b + OFF);
        if (vr && pa) av = __ldg(b + OFF - 1);
        if (vr && pe) dv = __ldg(b + OFF + 2);
        u64 va = pack2(av,av), vb = pack2(bc.x,bc.x), vc = pack2(bc.y,bc.y), vd = pack2(dv,dv);
        const ulonglong2* wt = wci + (i*9 + j*3)*CPH;
        #pragma unroll
        for (int k = 0; k < 3; k++){
          u64 q0 = (k==0) ? va : (k==1) ? vb : vc;
          u64 q1 = (k==0) ? vb : (k==1) ? vc : vd;
          #pragma unroll
          for (int p2 = 0; p2 < CPH; p2++){
            ulonglong2 wv = wt[k*CPH + p2];
            fma2(acc0[2*p2  ], q0, wv.x);
            fma2(acc0[2*p2+1], q0, wv.y);
            fma2(acc1[2*p2  ], q1, wv.x);
            fma2(acc1[2*p2+1], q1, wv.y);
          }
        }
      }
    }
  }

  float r0[2*CP], r1[2*CP];
  #pragma unroll
  for (int p = 0; p < CP; p++){
    unpack2(r0[2*p], r0[2*p+1], acc0[p]);
    unpack2(r1[2*p], r1[2*p+1], acc1[p]);
  }
  if (RELU){
    #pragma unroll
    for (int c = 0; c < COUT; c++){ r0[c] = fmaxf(r0[c],0.f); r1[c] = fmaxf(r1[c],0.f); }
  }

  if (NORM){
    float s0 = 0.f, s1 = 0.f;
    #pragma unroll
    for (int c = 0; c < COUT; c++){ s0 += fabsf(r0[c]); s1 += fabsf(r1[c]); }
    float i0 = 1.f / fmaxf(s0, 1e-12f);
    float i1 = 1.f / fmaxf(s1, 1e-12f);
    #pragma unroll
    for (int c = 0; c < COUT; c++){
      float2 o; o.x = r0[c]*i0; o.y = r1[c]*i1;
      *reinterpret_cast<float2*>(out + c*VOL + base) = o;
    }
  } else {
    #pragma unroll
    for (int c = 0; c < COUT; c++){
      float2 o; o.x = r0[c]; o.y = r1[c];
      *reinterpret_cast<float2*>(out + c*VOL + base) = o;
    }
  }
}

// ============================================================================
// 3x3x3 conv, CIN=8, 4-voxel threads (COUT=8 / COUT=1).
// Window = LDG.128 + 2 scalars per stencil row; weight LDS amortized over 4
// voxels. Halves L1 wavefronts/voxel vs 2-voxel version (which was 88% L1).
// Grid: (32, 128); block 128 = 4 h-rows x 32 w-quads.
// ============================================================================
template<int COUT, bool RELU>
__global__ void __launch_bounds__(128)
conv3d4_k(const float* __restrict__ x, const float* __restrict__ wgt,
          const float* __restrict__ bias, float* __restrict__ out)
{
  constexpr int CPH = (COUT + 3) / 4;
  constexpr int CP  = 2*CPH;
  __shared__ ulonglong2 wp[8*27*CPH];
  const int tid = threadIdx.x;
  const int h  = 4*blockIdx.x + (tid >> 5);
  const int w0 = (tid & 31)*4;
  const int d  = blockIdx.y;

  for (int i = tid; i < 8*27*CPH; i += 128){
    int p2 = i % CPH; int rest = i / CPH; int t = rest % 27; int ci = rest / 27;
    float c0 = (4*p2+0 < COUT) ? wgt[((4*p2+0)*8 + ci)*27 + t] : 0.f;
    float c1 = (4*p2+1 < COUT) ? wgt[((4*p2+1)*8 + ci)*27 + t] : 0.f;
    float c2 = (4*p2+2 < COUT) ? wgt[((4*p2+2)*8 + ci)*27 + t] : 0.f;
    float c3 = (4*p2+3 < COUT) ? wgt[((4*p2+3)*8 + ci)*27 + t] : 0.f;
    wp[i] = make_ulonglong2(pack2(c0,c1), pack2(c2,c3));
  }
  __syncthreads();

  u64 acc[4][CP];
  #pragma unroll
  for (int p = 0; p < CP; p++){
    float blo = (bias && 2*p   < COUT) ? bias[2*p]   : 0.f;
    float bhi = (bias && 2*p+1 < COUT) ? bias[2*p+1] : 0.f;
    u64 bp = pack2(blo, bhi);
    #pragma unroll
    for (int v = 0; v < 4; v++) acc[v][p] = bp;
  }

  const bool pd[3] = { d > 0, true, d < 127 };
  const bool ph[3] = { h > 0, true, h < 127 };
  const bool pa = w0 > 0, pe = w0 < 124;
  const int base = d*PLANE + h*128 + w0;

  #pragma unroll 1
  for (int ci = 0; ci < 8; ci++){
    const float* b = x + ci*VOL + base;
    const ulonglong2* wci = wp + ci*27*CPH;
    #pragma unroll
    for (int r = 0; r < 9; r++){
      const int i = r/3, j = r%3;
      const int OFF = (i-1)*PLANE + (j-1)*128;
      const bool vr = pd[i] && ph[j];
      float4 m = make_float4(0.f,0.f,0.f,0.f);
      float lo = 0.f, hi = 0.f;
      if (vr)       m  = *reinterpret_cast<const float4*>(b + OFF);
      if (vr && pa) lo = __ldg(b + OFF - 1);
      if (vr && pe) hi = __ldg(b + OFF + 4);
      u64 xp[6] = { pack2(lo,lo), pack2(m.x,m.x), pack2(m.y,m.y),
                    pack2(m.z,m.z), pack2(m.w,m.w), pack2(hi,hi) };
      const ulonglong2* wt = wci + r*3*CPH;
      #pragma unroll
      for (int k = 0; k < 3; k++){
        #pragma unroll
        for (int p2 = 0; p2 < CPH; p2++){
          ulonglong2 wv = wt[k*CPH + p2];
          #pragma unroll
          for (int v = 0; v < 4; v++){
            fma2(acc[v][2*p2  ], xp[v+k], wv.x);
            fma2(acc[v][2*p2+1], xp[v+k], wv.y);
          }
        }
      }
    }
  }

  float res[4][2*CP];
  #pragma unroll
  for (int v = 0; v < 4; v++){
    #pragma unroll
    for (int p = 0; p < CP; p++) unpack2(res[v][2*p], res[v][2*p+1], acc[v][p]);
  }
  if (RELU){
    #pragma unroll
    for (int v = 0; v < 4; v++)
      #pragma unroll
      for (int c = 0; c < COUT; c++) res[v][c] = fmaxf(res[v][c], 0.f);
  }
  #pragma unroll
  for (int c = 0; c < COUT; c++){
    float4 o = make_float4(res[0][c], res[1][c], res[2][c], res[3][c]);
    *reinterpret_cast<float4*>(out + c*VOL + base) = o;
  }
}

// ============================================================================
// Adaptive conv, SMEM-tiled, channel-pair fma2. (R11 winner, unchanged.)
// ============================================================================
template<int C, bool TANH>
__global__ void __launch_bounds__(256)
adapt_k(const float* __restrict__ x, const float* __restrict__ w27,
        float* __restrict__ out)
{
  const int tid = threadIdx.x;
  const int h0 = 2*blockIdx.x;
  const int d  = blockIdx.y;
  const int hs = tid >> 7;
  const int w  = tid & 127;
  const int idx = d*PLANE + (h0+hs)*128 + w;

  if constexpr (C == 8){
    __shared__ float2 tile[48*128];
    {
      const int sub  = tid >> 6;
      const int lane = tid & 63;
      #pragma unroll
      for (int it = 0; it < 12; it++){
        const int row = it*4 + sub;
        const int cp  = (row*43) >> 9;
        const int rm  = row - cp*12;
        const int di  = rm >> 2;
        const int hi  = rm & 3;
        const int dd  = d + di - 1;
        const int hh  = h0 + hi - 1;
        float2 a = make_float2(0.f,0.f), b = make_float2(0.f,0.f);
        if ((unsigned)dd < 128u && (unsigned)hh < 128u){
          const float* p0 = x + (2*cp)*VOL + (dd*128 + hh)*128 + lane*2;
          a = *reinterpret_cast<const float2*>(p0);
          b = *reinterpret_cast<const float2*>(p0 + VOL);
        }
        float4 st = make_float4(a.x, b.x, a.y, b.y);
        *reinterpret_cast<float4*>(tile + row*128 + lane*2) = st;
      }
    }

    float wv[27];
    #pragma unroll
    for (int t = 0; t < 27; t++) wv[t] = __ldg(w27 + t*VOL + idx);

    __syncthreads();

    const bool wa = (w > 0), we = (w < 127);
    u64 acc[4] = {0ull,0ull,0ull,0ull};

    #pragma unroll
    for (int i = 0; i < 3; i++){
      #pragma unroll
      for (int j = 0; j < 3; j++){
        const float2* rp = tile + (i*4 + hs + j)*128 + w;
        #pragma unroll
        for (int k = 0; k < 3; k++){
          const int t = i*9 + j*3 + k;
          const u64 wpk = pack2(wv[t], wv[t]);
          const bool ok = (k==0) ? wa : (k==2) ? we : true;
          #pragma unroll
          for (int cp = 0; cp < 4; cp++){
            float2 v = make_float2(0.f,0.f);
            if (ok) v = rp[cp*1536 + (k-1)];
            fma2(acc[cp], wpk, *reinterpret_cast<const u64*>(&v));
          }
        }
      }
    }

    #pragma unroll
    for (int cp = 0; cp < 4; cp++){
      float r0, r1; unpack2(r0, r1, acc[cp]);
      out[(2*cp  )*VOL + idx] = TANH ? tanhf(r0) : r0;
      out[(2*cp+1)*VOL + idx] = TANH ? tanhf(r1) : r1;
    }
  } else {
    __shared__ float tile[12*128];
    {
      const int sub  = tid >> 5;
      const int lane = tid & 31;
      #pragma unroll
      for (int it = 0; it < 2; it++){
        const int row = it*8 + sub;
        if (row < 12){
          const int di = row >> 2, hi = row & 3;
          const int dd = d + di - 1, hh = h0 + hi - 1;
          float4 v = make_float4(0.f,0.f,0.f,0.f);
          if ((unsigned)dd < 128u && (unsigned)hh < 128u)
            v = *reinterpret_cast<const float4*>(x + (dd*128 + hh)*128 + lane*4);
          *reinterpret_cast<float4*>(tile + row*128 + lane*4) = v;
        }
      }
    }

    float wv[27];
    #pragma unroll
    for (int t = 0; t < 27; t++) wv[t] = __ldg(w27 + t*VOL + idx);

    __syncthreads();

    const bool wa = (w > 0), we = (w < 127);
    float s0 = 0.f, s1 = 0.f, s2 = 0.f;
    #pragma unroll
    for (int i = 0; i < 3; i++){
      #pragma unroll
      for (int j = 0; j < 3; j++){
        const float* rp = tile + (i*4 + hs + j)*128 + w;
        const int t = i*9 + j*3;
        float va = 0.f, vc = 0.f;
        if (wa) va = rp[-1];
        if (we) vc = rp[ 1];
        s0 = fmaf(wv[t  ], va,    s0);
        s1 = fmaf(wv[t+1], rp[0], s1);
        s2 = fmaf(wv[t+2], vc,    s2);
      }
    }
    float acc = s0 + s1 + s2;
    out[idx] = TANH ? tanhf(acc) : acc;
  }
}

extern "C" void kernel_launch(void* const* d_in, const int* in_sizes, int n_in,
                              void* d_out, int out_size)
{
  const float* x    = (const float*)d_in[0];
  const float* a1w1 = (const float*)d_in[1];
  const float* a1b1 = (const float*)d_in[2];
  const float* a1w2 = (const float*)d_in[3];
  const float* a2w1 = (const float*)d_in[4];
  const float* a2b1 = (const float*)d_in[5];
  const float* a2w2 = (const float*)d_in[6];
  const float* a3w1 = (const float*)d_in[7];
  const float* a3b1 = (const float*)d_in[8];
  const float* a3w2 = (const float*)d_in[9];
  const float* midw = (const float*)d_in[10];
  const float* midb = (const float*)d_in[11];
  const float* outw = (const float*)d_in[12];
  const float* outb = (const float*)d_in[13];
  float* y = (float*)d_out;

  float *H, *A, *W, *F;
  cudaGetSymbolAddress((void**)&H, g_H);
  cudaGetSymbolAddress((void**)&A, g_A);
  cudaGetSymbolAddress((void**)&W, g_W);
  cudaGetSymbolAddress((void**)&F, g_F);

  dim3 gc(64, 128), bc(128);        // 2-voxel conv (COUT=27)
  dim3 g4(32, 128);                 // 4-voxel conv (COUT=8/1)
  dim3 ga(64, 128), ba(256);        // adapt

  // Shims: capture slot is the 4th launch -> aim it at conv27.
  noop_k<<<1,32>>>();
  noop_k<<<1,32>>>();

  // ---- adaptive block 1 (input x) ----
  conv3d4_k<8, true ><<<g4,bc>>>(x, a1w1, a1b1, H);            // h1      (3rd)
  conv3d_k<27, false, true ><<<gc,bc>>>(H, a1w2, nullptr, W);  // W field (4th = profiled)
  adapt_k<8, false><<<ga,ba>>>(x, W, A);
  adapt_k<8, false><<<ga,ba>>>(A, W, H);
  adapt_k<8, false><<<ga,ba>>>(H, W, A);                       // block1 out = A

  // ---- mid conv ----
  conv3d4_k<8, false><<<g4,bc>>>(A, midw, midb, H);            // mid = H

  // ---- adaptive block 2 (input mid) ----
  conv3d4_k<8, true ><<<g4,bc>>>(H, a2w1, a2b1, A);            // h2
  conv3d_k<27, false, true ><<<gc,bc>>>(A, a2w2, nullptr, W);
  adapt_k<8, false><<<ga,ba>>>(H, W, A);
  adapt_k<8, false><<<ga,ba>>>(A, W, H);
  adapt_k<8, false><<<ga,ba>>>(H, W, A);                       // mid2 = A

  // ---- out conv + adaptive block 3 (weights from mid2, data 1-channel) ----
  conv3d4_k<1, false><<<g4,bc>>>(A, outw, outb, F);            // final (1ch)
  conv3d4_k<8, true ><<<g4,bc>>>(A, a3w1, a3b1, H);            // h3 from mid2
  conv3d_k<27, false, true ><<<gc,bc>>>(H, a3w2, nullptr, W);
  adapt_k<1, false><<<ga,ba>>>(F, W, y);
  adapt_k<1, false><<<ga,ba>>>(y, W, F);
  adapt_k<1, true ><<<ga,ba>>>(F, W, y);                       // + tanh
}